// round 7
// baseline (speedup 1.0000x reference)
#include <cuda_runtime.h>

typedef unsigned int u32;

#define IN_PN  20000
#define OUT_PN 5000
#define MNB    9
#define CIN    32
#define COUT   64
#define SLOT   36                 /* padded row stride (floats) */
#define TILEF  (64 * SLOT)        /* floats per 64x32 tile */
#define TB     (TILEF * 4)        /* tile bytes = 9216 */

__device__ __forceinline__ u32 tf32c(float x) {
    u32 r; asm("cvt.rna.tf32.f32 %0, %1;" : "=r"(r) : "f"(x)); return r;
}
__device__ __forceinline__ void mma8(float d[4], u32 a0, u32 a1, u32 a2, u32 a3,
                                     u32 b0, u32 b1) {
    asm("mma.sync.aligned.m16n8k8.row.col.f32.tf32.tf32.f32 "
        "{%0,%1,%2,%3}, {%4,%5,%6,%7}, {%8,%9}, {%0,%1,%2,%3};"
        : "+f"(d[0]), "+f"(d[1]), "+f"(d[2]), "+f"(d[3])
        : "r"(a0), "r"(a1), "r"(a2), "r"(a3), "r"(b0), "r"(b1));
}
__device__ __forceinline__ void ldsm4(u32 r[4], u32 addr) {
    asm volatile("ldmatrix.sync.aligned.m8n8.x4.shared.b16 {%0,%1,%2,%3}, [%4];"
                 : "=r"(r[0]), "=r"(r[1]), "=r"(r[2]), "=r"(r[3]) : "r"(addr));
}
__device__ __forceinline__ void cpasync16(u32 dst, const float* src) {
    asm volatile("cp.async.cg.shared.global [%0], [%1], 16;" :: "r"(dst), "l"(src));
}
__device__ __forceinline__ void cpcommit() {
    asm volatile("cp.async.commit_group;" ::: "memory");
}
__device__ __forceinline__ void cpwait0() {
    asm volatile("cp.async.wait_group 0;" ::: "memory");
}

// one 64x64x32 slice for this warp's 32b x 32o tile.
// A tile: pre-converted tf32 bits. W tile: raw fp32, cvt at read (idempotent
// if already tf32). aA0/aA1: ldmatrix lane addrs for b-halves; wA likewise.
__device__ __forceinline__ void slice_mma(u32 aA0, u32 aA1, u32 wA,
                                          float acc[2][4][4])
{
    #pragma unroll
    for (int kk = 0; kk < 4; kk++) {
        u32 a0[4], a1[4], w0[4], w1[4];
        ldsm4(a0, aA0); ldsm4(a1, aA1);
        ldsm4(w0, wA);  ldsm4(w1, wA + 16);
        aA0 += 32; aA1 += 32; wA += 32;
        #pragma unroll
        for (int j = 0; j < 4; j++) {
            u32 b0 = tf32c(__uint_as_float(w0[j]));
            u32 b1 = tf32c(__uint_as_float(w1[j]));
            mma8(acc[0][j], a0[0], a0[1], a0[2], a0[3], b0, b1);
            mma8(acc[1][j], a1[0], a1[1], a1[2], a1[3], b0, b1);
        }
    }
}

__device__ __forceinline__ void ldg16(float v[16], const float* __restrict__ src, bool valid) {
    if (valid) {
        #pragma unroll
        for (int j = 0; j < 4; j++) {
            float4 a = ((const float4*)src)[j];
            v[4*j+0] = a.x; v[4*j+1] = a.y; v[4*j+2] = a.z; v[4*j+3] = a.w;
        }
    } else {
        #pragma unroll
        for (int i = 0; i < 16; i++) v[i] = 0.0f;
    }
}
__device__ __forceinline__ void sts16(float* dst, const float v[16], float sc) {
    #pragma unroll
    for (int j = 0; j < 4; j++) {
        uint4 x;
        x.x = tf32c(v[4*j+0] * sc); x.y = tf32c(v[4*j+1] * sc);
        x.z = tf32c(v[4*j+2] * sc); x.w = tf32c(v[4*j+3] * sc);
        ((uint4*)dst)[j] = x;
    }
}

__global__ __launch_bounds__(128, 6)
void pconv_mma(const float* __restrict__ in_pc,
               const int*   __restrict__ nid_g,
               const float* __restrict__ wts,
               const float* __restrict__ bias,
               const float* __restrict__ pnb,
               const float* __restrict__ wres,
               float* __restrict__ out)
{
    // layout: A0 @0, A1 @TILEF, W0 @2*TILEF, W1 @3*TILEF
    __shared__ float sm[4 * TILEF + 32];
    float* pm_s  = sm + 4 * TILEF;
    int*   nid_s = (int*)(sm + 4 * TILEF + 16);

    const int tid  = threadIdx.x;
    const int lane = tid & 31;
    const int wid  = tid >> 5;
    const int p    = blockIdx.x;

    const int bg  = (wid >> 1) * 32;
    const int og  = (wid & 1) * 32;
    const int g   = lane >> 2;
    const int tig = lane & 3;

    const int srow = tid >> 1;
    const int scol = (tid & 1) * 16;

    if (tid < MNB) {
        int nv = nid_g[p * MNB + tid];
        nid_s[tid] = nv;
        pm_s[tid] = (nv != IN_PN) ? fabsf(pnb[p * MNB + tid]) : 0.0f;
    }
    __syncthreads();
    if (tid == 0) {
        float s = 1e-8f;
        #pragma unroll
        for (int m = 0; m < MNB; m++) s += pm_s[m];
        float inv = 1.0f / s;
        #pragma unroll
        for (int m = 0; m < MNB; m++) pm_s[m] *= inv;
    }
    __syncthreads();

    const float* wp    = wts + (size_t)p * (MNB * CIN * COUT);
    const float* inrow = in_pc + (size_t)srow * (IN_PN * CIN) + scol;
    const u32 smb = (u32)__cvta_generic_to_shared(sm);

    // ldmatrix lane addresses (within A0 / W0 tiles)
    const u32 aFrag = smb + (u32)(bg + (lane & 15)) * (SLOT * 4u) + (u32)(lane >> 4) * 16u;
    const u32 wFrag = smb + (u32)(2 * TB) + (u32)(og + lane) * (SLOT * 4u);
    const u32 aHalf = 16u * SLOT * 4u;          // bb=1 row offset (16 rows)
    // staging byte offset within a tile
    const u32 stOff = (u32)(srow * SLOT + scol) * 4u;

    float rs[16];
    #pragma unroll
    for (int i = 0; i < 16; i++) rs[i] = 0.0f;
    float va[16];

    // ---- prologue: W0 via cp.async, In0 via LDG->cvt->STS ----
    {
        const float* wsrc = wp + (size_t)srow * CIN + scol;
        u32 wdst = smb + 2u * TB + stOff;
        #pragma unroll
        for (int j = 0; j < 4; j++) cpasync16(wdst + 16u * j, wsrc + 4 * j);
        cpcommit();

        int nv = nid_s[0];
        ldg16(va, inrow + (u32)nv * CIN, nv != IN_PN);
        float pmv = pm_s[0];
        #pragma unroll
        for (int i = 0; i < 16; i++) rs[i] = fmaf(pmv, va[i], rs[i]);
        sts16(sm + srow * SLOT + scol, va, 1.0f);
        cpwait0();
    }
    __syncthreads();

    float acc[2][4][4];
    #pragma unroll
    for (int b = 0; b < 2; b++)
        #pragma unroll
        for (int j = 0; j < 4; j++)
            #pragma unroll
            for (int e = 0; e < 4; e++) acc[b][j][e] = 0.0f;

    #pragma unroll 1
    for (int m = 0; m < MNB; m++) {
        const u32 cOff = (m & 1) ? (u32)TB : 0u;   // current tile byte offset
        const u32 nOff = (u32)TB - cOff;           // next tile byte offset

        if (m < MNB - 1) {
            const float* wsrc = wp + (size_t)(m + 1) * (CIN * COUT)
                              + (size_t)srow * CIN + scol;
            u32 wdst = smb + 2u * TB + nOff + stOff;
            #pragma unroll
            for (int j = 0; j < 4; j++) cpasync16(wdst + 16u * j, wsrc + 4 * j);
            cpcommit();
        }

        slice_mma(aFrag + cOff, aFrag + cOff + aHalf, wFrag + cOff, acc);

        if (m < MNB - 1) {
            int nv = nid_s[m + 1];
            ldg16(va, inrow + (u32)nv * CIN, nv != IN_PN);
            float pmv = pm_s[m + 1];
            #pragma unroll
            for (int i = 0; i < 16; i++) rs[i] = fmaf(pmv, va[i], rs[i]);
            sts16(sm + (nOff >> 2) + srow * SLOT + scol, va, 1.0f);
            cpwait0();
            __syncthreads();
        }
    }

    // ---- residual slice into freed buffers A1/W1 (last slice used A0/W0) ----
    const float C = 0.70710678118654752f;   // sqrt(0.5)
    sts16(sm + TILEF + srow * SLOT + scol, rs, 1.0f);
    {
        float vw[16];
        ldg16(vw, wres + (size_t)srow * CIN + scol, true);
        sts16(sm + 3 * TILEF + srow * SLOT + scol, vw, C);  // pre-scaled sqrt(RR)
    }

    // acc <- C * elu(acc + bias) in the shadow of staging
    const float* brow = bias + (size_t)p * COUT;
    #pragma unroll
    for (int j = 0; j < 4; j++) {
        const int o0 = og + 8 * j + 2 * tig;
        float2 bb = *(const float2*)(brow + o0);
        #pragma unroll
        for (int b = 0; b < 2; b++) {
            float x0 = acc[b][j][0] + bb.x;
            float x1 = acc[b][j][1] + bb.y;
            float x2 = acc[b][j][2] + bb.x;
            float x3 = acc[b][j][3] + bb.y;
            x0 = (x0 > 0.0f) ? x0 : expm1f(x0);
            x1 = (x1 > 0.0f) ? x1 : expm1f(x1);
            x2 = (x2 > 0.0f) ? x2 : expm1f(x2);
            x3 = (x3 > 0.0f) ? x3 : expm1f(x3);
            acc[b][j][0] = C * x0; acc[b][j][1] = C * x1;
            acc[b][j][2] = C * x2; acc[b][j][3] = C * x3;
        }
    }
    __syncthreads();

    // residual MMA accumulates in place (A1/W1)
    slice_mma(aFrag + TB, aFrag + TB + aHalf, wFrag + TB, acc);

    // ---- store: out[b][p][o] ----
    #pragma unroll
    for (int j = 0; j < 4; j++) {
        const int o0 = og + 8 * j + 2 * tig;
        #pragma unroll
        for (int b = 0; b < 2; b++) {
            const int r0 = bg + 16 * b + g;
            float2 v0 = { acc[b][j][0], acc[b][j][1] };
            float2 v1 = { acc[b][j][2], acc[b][j][3] };
            *(float2*)(out + ((size_t)r0       * OUT_PN + p) * COUT + o0) = v0;
            *(float2*)(out + ((size_t)(r0 + 8) * OUT_PN + p) * COUT + o0) = v1;
        }
    }
}

extern "C" void kernel_launch(void* const* d_in, const int* in_sizes, int n_in,
                              void* d_out, int out_size)
{
    const float* in_pc = (const float*)d_in[0];
    const int*   nid   = (const int*)  d_in[1];
    const float* wts   = (const float*)d_in[2];
    const float* bias  = (const float*)d_in[3];
    const float* pnb   = (const float*)d_in[4];
    const float* wres  = (const float*)d_in[5];
    float* out = (float*)d_out;

    pconv_mma<<<OUT_PN, 128>>>(in_pc, nid, wts, bias, pnb, wres, out);
}

// round 8
// speedup vs baseline: 1.2348x; 1.2348x over previous
#include <cuda_runtime.h>

typedef unsigned int u32;

#define IN_PN  20000
#define OUT_PN 5000
#define MNB    9
#define CIN    32
#define COUT   64
#define SLOT   36                 /* padded row stride (floats) */
#define TILEF  (64 * SLOT)        /* floats per 64x32 tile */
#define TB     (TILEF * 4)        /* tile bytes = 9216 */

__device__ __forceinline__ u32 tf32c(float x) {
    u32 r; asm("cvt.rna.tf32.f32 %0, %1;" : "=r"(r) : "f"(x)); return r;
}
__device__ __forceinline__ void mma8(float d[4], u32 a0, u32 a1, u32 a2, u32 a3,
                                     u32 b0, u32 b1) {
    asm("mma.sync.aligned.m16n8k8.row.col.f32.tf32.tf32.f32 "
        "{%0,%1,%2,%3}, {%4,%5,%6,%7}, {%8,%9}, {%0,%1,%2,%3};"
        : "+f"(d[0]), "+f"(d[1]), "+f"(d[2]), "+f"(d[3])
        : "r"(a0), "r"(a1), "r"(a2), "r"(a3), "r"(b0), "r"(b1));
}
__device__ __forceinline__ void ldsm4(u32 r[4], u32 addr) {
    asm volatile("ldmatrix.sync.aligned.m8n8.x4.shared.b16 {%0,%1,%2,%3}, [%4];"
                 : "=r"(r[0]), "=r"(r[1]), "=r"(r[2]), "=r"(r[3]) : "r"(addr));
}
__device__ __forceinline__ void cpasync16(u32 dst, const float* src) {
    asm volatile("cp.async.cg.shared.global [%0], [%1], 16;" :: "r"(dst), "l"(src));
}
__device__ __forceinline__ void cpcommit() {
    asm volatile("cp.async.commit_group;" ::: "memory");
}
__device__ __forceinline__ void cpwait0() {
    asm volatile("cp.async.wait_group 0;" ::: "memory");
}

// one 64x64x32 slice for this warp's 32b x 32o tile.
// A tile: pre-converted tf32 bits (ldmatrix passthrough).
// W tile: raw fp32, cvt at read (idempotent if already tf32).
__device__ __forceinline__ void slice_mma(u32 aA0, u32 aA1, u32 wA,
                                          float acc[2][4][4])
{
    #pragma unroll
    for (int kk = 0; kk < 4; kk++) {
        u32 a0[4], a1[4], w0[4], w1[4];
        ldsm4(a0, aA0); ldsm4(a1, aA1);
        ldsm4(w0, wA);  ldsm4(w1, wA + 16);
        aA0 += 32; aA1 += 32; wA += 32;
        #pragma unroll
        for (int j = 0; j < 4; j++) {
            u32 b0 = tf32c(__uint_as_float(w0[j]));
            u32 b1 = tf32c(__uint_as_float(w1[j]));
            mma8(acc[0][j], a0[0], a0[1], a0[2], a0[3], b0, b1);
            mma8(acc[1][j], a1[0], a1[1], a1[2], a1[3], b0, b1);
        }
    }
}

__device__ __forceinline__ void ldg16(float v[16], const float* __restrict__ src, bool valid) {
    if (valid) {
        #pragma unroll
        for (int j = 0; j < 4; j++) {
            float4 a = ((const float4*)src)[j];
            v[4*j+0] = a.x; v[4*j+1] = a.y; v[4*j+2] = a.z; v[4*j+3] = a.w;
        }
    } else {
        #pragma unroll
        for (int i = 0; i < 16; i++) v[i] = 0.0f;
    }
}
__device__ __forceinline__ void sts16(float* dst, const float v[16], float sc) {
    #pragma unroll
    for (int j = 0; j < 4; j++) {
        uint4 x;
        x.x = tf32c(v[4*j+0] * sc); x.y = tf32c(v[4*j+1] * sc);
        x.z = tf32c(v[4*j+2] * sc); x.w = tf32c(v[4*j+3] * sc);
        ((uint4*)dst)[j] = x;
    }
}

__global__ __launch_bounds__(128, 5)
void pconv_mma(const float* __restrict__ in_pc,
               const int*   __restrict__ nid_g,
               const float* __restrict__ wts,
               const float* __restrict__ bias,
               const float* __restrict__ pnb,
               const float* __restrict__ wres,
               float* __restrict__ out)
{
    // layout: A0 @0, A1 @TILEF, W0 @2*TILEF, W1 @3*TILEF
    __shared__ float sm[4 * TILEF + 32];
    float* pm_s  = sm + 4 * TILEF;
    int*   nid_s = (int*)(sm + 4 * TILEF + 16);

    const int tid  = threadIdx.x;
    const int lane = tid & 31;
    const int wid  = tid >> 5;
    const int p    = blockIdx.x;

    const int bg  = (wid >> 1) * 32;
    const int og  = (wid & 1) * 32;
    const int g   = lane >> 2;
    const int tig = lane & 3;

    const int srow = tid >> 1;
    const int scol = (tid & 1) * 16;

    if (tid < MNB) {
        int nv = nid_g[p * MNB + tid];
        nid_s[tid] = nv;
        pm_s[tid] = (nv != IN_PN) ? fabsf(pnb[p * MNB + tid]) : 0.0f;
    }
    __syncthreads();
    if (tid == 0) {
        float s = 1e-8f;
        #pragma unroll
        for (int m = 0; m < MNB; m++) s += pm_s[m];
        float inv = 1.0f / s;
        #pragma unroll
        for (int m = 0; m < MNB; m++) pm_s[m] *= inv;
    }
    __syncthreads();

    const float* wp    = wts + (size_t)p * (MNB * CIN * COUT);
    const float* inrow = in_pc + (size_t)srow * (IN_PN * CIN) + scol;
    const u32 smb = (u32)__cvta_generic_to_shared(sm);

    // ldmatrix lane addresses (within A0 / W0 tiles) — verified mapping (R7)
    const u32 aFrag = smb + (u32)(bg + (lane & 15)) * (SLOT * 4u) + (u32)(lane >> 4) * 16u;
    const u32 wFrag = smb + (u32)(2 * TB) + (u32)(og + lane) * (SLOT * 4u);
    const u32 aHalf = 16u * SLOT * 4u;
    const u32 stOff = (u32)(srow * SLOT + scol) * 4u;

    float rs[16];
    #pragma unroll
    for (int i = 0; i < 16; i++) rs[i] = 0.0f;
    float va[16];

    // ---- prologue: W0 via cp.async, In0 via LDG->cvt->STS ----
    {
        const float* wsrc = wp + (size_t)srow * CIN + scol;
        u32 wdst = smb + 2u * TB + stOff;
        #pragma unroll
        for (int j = 0; j < 4; j++) cpasync16(wdst + 16u * j, wsrc + 4 * j);
        cpcommit();

        int nv = nid_s[0];
        ldg16(va, inrow + (u32)nv * CIN, nv != IN_PN);
        float pmv = pm_s[0];
        #pragma unroll
        for (int i = 0; i < 16; i++) rs[i] = fmaf(pmv, va[i], rs[i]);
        sts16(sm + srow * SLOT + scol, va, 1.0f);
        cpwait0();
    }
    __syncthreads();

    float acc[2][4][4];
    #pragma unroll
    for (int b = 0; b < 2; b++)
        #pragma unroll
        for (int j = 0; j < 4; j++)
            #pragma unroll
            for (int e = 0; e < 4; e++) acc[b][j][e] = 0.0f;

    #pragma unroll 1
    for (int m = 0; m < MNB; m++) {
        const u32 cOff = (m & 1) ? (u32)TB : 0u;   // current tile byte offset
        const u32 nOff = (u32)TB - cOff;           // next tile byte offset

        if (m < MNB - 1) {
            // issue W cp.async and In LDG EARLY: latency hides under slice_mma
            const float* wsrc = wp + (size_t)(m + 1) * (CIN * COUT)
                              + (size_t)srow * CIN + scol;
            u32 wdst = smb + 2u * TB + nOff + stOff;
            #pragma unroll
            for (int j = 0; j < 4; j++) cpasync16(wdst + 16u * j, wsrc + 4 * j);
            cpcommit();

            int nv = nid_s[m + 1];
            ldg16(va, inrow + (u32)nv * CIN, nv != IN_PN);
        }

        slice_mma(aFrag + cOff, aFrag + cOff + aHalf, wFrag + cOff, acc);

        if (m < MNB - 1) {
            float pmv = pm_s[m + 1];
            #pragma unroll
            for (int i = 0; i < 16; i++) rs[i] = fmaf(pmv, va[i], rs[i]);
            sts16(sm + (nOff >> 2) + srow * SLOT + scol, va, 1.0f);
            cpwait0();
            __syncthreads();
        }
    }

    // ---- residual slice into freed buffers A1/W1 (last slice used A0/W0) ----
    const float C = 0.70710678118654752f;   // sqrt(0.5)
    sts16(sm + TILEF + srow * SLOT + scol, rs, 1.0f);
    {
        float vw[16];
        ldg16(vw, wres + (size_t)srow * CIN + scol, true);
        sts16(sm + 3 * TILEF + srow * SLOT + scol, vw, C);  // pre-scaled sqrt(RR)
    }

    // acc <- C * elu(acc + bias) in the shadow of staging
    const float* brow = bias + (size_t)p * COUT;
    #pragma unroll
    for (int j = 0; j < 4; j++) {
        const int o0 = og + 8 * j + 2 * tig;
        float2 bb = *(const float2*)(brow + o0);
        #pragma unroll
        for (int b = 0; b < 2; b++) {
            float x0 = acc[b][j][0] + bb.x;
            float x1 = acc[b][j][1] + bb.y;
            float x2 = acc[b][j][2] + bb.x;
            float x3 = acc[b][j][3] + bb.y;
            x0 = (x0 > 0.0f) ? x0 : expm1f(x0);
            x1 = (x1 > 0.0f) ? x1 : expm1f(x1);
            x2 = (x2 > 0.0f) ? x2 : expm1f(x2);
            x3 = (x3 > 0.0f) ? x3 : expm1f(x3);
            acc[b][j][0] = C * x0; acc[b][j][1] = C * x1;
            acc[b][j][2] = C * x2; acc[b][j][3] = C * x3;
        }
    }
    __syncthreads();

    // residual MMA accumulates in place (A1/W1, wres pre-scaled)
    slice_mma(aFrag + TB, aFrag + TB + aHalf, wFrag + TB, acc);

    // ---- store: out[b][p][o] ----
    #pragma unroll
    for (int j = 0; j < 4; j++) {
        const int o0 = og + 8 * j + 2 * tig;
        #pragma unroll
        for (int b = 0; b < 2; b++) {
            const int r0 = bg + 16 * b + g;
            float2 v0 = { acc[b][j][0], acc[b][j][1] };
            float2 v1 = { acc[b][j][2], acc[b][j][3] };
            *(float2*)(out + ((size_t)r0       * OUT_PN + p) * COUT + o0) = v0;
            *(float2*)(out + ((size_t)(r0 + 8) * OUT_PN + p) * COUT + o0) = v1;
        }
    }
}

extern "C" void kernel_launch(void* const* d_in, const int* in_sizes, int n_in,
                              void* d_out, int out_size)
{
    const float* in_pc = (const float*)d_in[0];
    const int*   nid   = (const int*)  d_in[1];
    const float* wts   = (const float*)d_in[2];
    const float* bias  = (const float*)d_in[3];
    const float* pnb   = (const float*)d_in[4];
    const float* wres  = (const float*)d_in[5];
    float* out = (float*)d_out;

    pconv_mma<<<OUT_PN, 128>>>(in_pc, nid, wts, bias, pnb, wres, out);
}